// round 1
// baseline (speedup 1.0000x reference)
#include <cuda_runtime.h>

// ---------------------------------------------------------------------------
// Fully fused MLP-Mixer: conv1x1+fc0 -> 8 layers x 2 repeats x (token, channel)
// -> fc1 + avgpool + fcout.  One CTA = 256 threads = 8 warps, each warp owns
// 2 batch elements whose 32x32 h tiles live in SMEM (padded to [32][33]).
// All inner products use packed fma.rn.f32x2 (FFMA2) with LDS.128 weight feeds.
// ---------------------------------------------------------------------------

#define MIX_EPS 1e-5f

// ---- SMEM layout (in floats) ----
#define OFF_W11   0        // 8192  (also fc0_w / fc1_w)
#define OFF_W12T  8192     // 256*36 = 9216
#define OFF_W21   17408    // 8192  (also fcout_w)
#define OFF_W22T  25600    // 9216
#define OFF_B11   34816    // 256   (also fc0_b / fc1_b)
#define OFF_B12   35072    // 32    (also fcout_b)
#define OFF_B21   35104    // 256
#define OFF_B22   35360    // 32
#define OFF_LN1G  35392
#define OFF_LN1B  35424
#define OFF_LN2G  35456
#define OFF_LN2B  35488
#define OFF_H     35520    // 16 elems * 1056
#define OFF_STATS 52416    // 8 warps * 2 elems * 64
#define SMEM_FLOATS 53440  // 213760 bytes

__device__ __forceinline__ float2 ffma2(float2 a, float2 b, float2 c) {
    unsigned long long au = *reinterpret_cast<unsigned long long*>(&a);
    unsigned long long bu = *reinterpret_cast<unsigned long long*>(&b);
    unsigned long long cu = *reinterpret_cast<unsigned long long*>(&c);
    unsigned long long du;
    asm("fma.rn.f32x2 %0, %1, %2, %3;" : "=l"(du) : "l"(au), "l"(bu), "l"(cu));
    return *reinterpret_cast<float2*>(&du);
}

__device__ __forceinline__ float hswish(float v) {
    return v * fminf(fmaxf(v + 3.0f, 0.0f), 6.0f) * (1.0f / 6.0f);
}

// One mixing branch on two elements owned by this warp.
// TOKEN=true : LN stats per row, lane works on its column (transposed view).
// TOKEN=false: lane works on its own row (LN + mix fully lane-local).
template <bool TOKEN>
__device__ __forceinline__ void mix_branch(
    float* h0, float* h1,
    const float* sW1, const float* sW2T,
    const float* sB1, const float* sB2,
    const float* sG, const float* sBb,
    float* st0, float* st1, int lane)
{
    float2 l0[16], l1[16];

    if (TOKEN) {
        // phase 1: per-row LN stats (lane = row), stash in scratch
        float s0 = 0.f, q0 = 0.f, s1 = 0.f, q1 = 0.f;
        #pragma unroll
        for (int j = 0; j < 32; j++) {
            float v = h0[lane * 33 + j]; s0 += v; q0 += v * v;
            float w = h1[lane * 33 + j]; s1 += w; q1 += w * w;
        }
        float m0 = s0 * 0.03125f, m1 = s1 * 0.03125f;
        float r0 = rsqrtf(fmaxf(q0 * 0.03125f - m0 * m0, 0.f) + MIX_EPS);
        float r1 = rsqrtf(fmaxf(q1 * 0.03125f - m1 * m1, 0.f) + MIX_EPS);
        st0[lane] = m0; st0[32 + lane] = r0;
        st1[lane] = m1; st1[32 + lane] = r1;
        __syncwarp();
        // phase 2: lane = column j; normalize column entries with per-row stats
        float gj = sG[lane], bj = sBb[lane];
        #pragma unroll
        for (int t = 0; t < 16; t++) {
            int k0 = 2 * t, k1 = 2 * t + 1;
            float mA = st0[k0], rA = st0[32 + k0];
            float mB = st0[k1], rB = st0[32 + k1];
            l0[t] = make_float2((h0[k0 * 33 + lane] - mA) * rA * gj + bj,
                                (h0[k1 * 33 + lane] - mB) * rB * gj + bj);
            float mC = st1[k0], rC = st1[32 + k0];
            float mD = st1[k1], rD = st1[32 + k1];
            l1[t] = make_float2((h1[k0 * 33 + lane] - mC) * rC * gj + bj,
                                (h1[k1 * 33 + lane] - mD) * rD * gj + bj);
        }
    } else {
        // lane = row i; LN over own row
        float s0 = 0.f, q0 = 0.f, s1 = 0.f, q1 = 0.f;
        #pragma unroll
        for (int j = 0; j < 32; j++) {
            float v = h0[lane * 33 + j]; s0 += v; q0 += v * v;
            float w = h1[lane * 33 + j]; s1 += w; q1 += w * w;
        }
        float m0 = s0 * 0.03125f, m1 = s1 * 0.03125f;
        float r0 = rsqrtf(fmaxf(q0 * 0.03125f - m0 * m0, 0.f) + MIX_EPS);
        float r1 = rsqrtf(fmaxf(q1 * 0.03125f - m1 * m1, 0.f) + MIX_EPS);
        #pragma unroll
        for (int t = 0; t < 16; t++) {
            int j0 = 2 * t, j1 = 2 * t + 1;
            float g0 = sG[j0], g1 = sG[j1], bb0 = sBb[j0], bb1 = sBb[j1];
            l0[t] = make_float2((h0[lane * 33 + j0] - m0) * r0 * g0 + bb0,
                                (h0[lane * 33 + j1] - m0) * r0 * g1 + bb1);
            l1[t] = make_float2((h1[lane * 33 + j0] - m1) * r1 * g0 + bb0,
                                (h1[lane * 33 + j1] - m1) * r1 * g1 + bb1);
        }
    }

    // out accumulators start at second-layer bias (residual added at the end)
    float2 out0[16], out1[16];
    #pragma unroll
    for (int t = 0; t < 16; t++) {
        float2 bv = *reinterpret_cast<const float2*>(sB2 + 2 * t);
        out0[t] = bv; out1[t] = bv;
    }

    // hidden loop over DIM=256
    for (int d = 0; d < 256; d++) {
        const float4* w1q = reinterpret_cast<const float4*>(sW1 + d * 32);
        float2 a0 = make_float2(0.f, 0.f), a0b = make_float2(0.f, 0.f);
        float2 a1 = make_float2(0.f, 0.f), a1b = make_float2(0.f, 0.f);
        #pragma unroll
        for (int q = 0; q < 8; q++) {
            float4 w = w1q[q];
            float2 wa = make_float2(w.x, w.y), wb = make_float2(w.z, w.w);
            a0  = ffma2(l0[2 * q],     wa, a0);
            a0b = ffma2(l0[2 * q + 1], wb, a0b);
            a1  = ffma2(l1[2 * q],     wa, a1);
            a1b = ffma2(l1[2 * q + 1], wb, a1b);
        }
        float bd = sB1[d];
        float hs0 = hswish(a0.x + a0.y + a0b.x + a0b.y + bd);
        float hs1 = hswish(a1.x + a1.y + a1b.x + a1b.y + bd);
        float2 hp0 = make_float2(hs0, hs0), hp1 = make_float2(hs1, hs1);
        const float4* w2q = reinterpret_cast<const float4*>(sW2T + d * 36);
        #pragma unroll
        for (int q = 0; q < 8; q++) {
            float4 w = w2q[q];
            float2 wa = make_float2(w.x, w.y), wb = make_float2(w.z, w.w);
            out0[2 * q]     = ffma2(hp0, wa, out0[2 * q]);
            out0[2 * q + 1] = ffma2(hp0, wb, out0[2 * q + 1]);
            out1[2 * q]     = ffma2(hp1, wa, out1[2 * q]);
            out1[2 * q + 1] = ffma2(hp1, wb, out1[2 * q + 1]);
        }
    }

    // residual add back into h
    if (TOKEN) {
        #pragma unroll
        for (int t = 0; t < 16; t++) {
            h0[(2 * t) * 33 + lane]     += out0[t].x;
            h0[(2 * t + 1) * 33 + lane] += out0[t].y;
            h1[(2 * t) * 33 + lane]     += out1[t].x;
            h1[(2 * t + 1) * 33 + lane] += out1[t].y;
        }
    } else {
        #pragma unroll
        for (int t = 0; t < 16; t++) {
            h0[lane * 33 + 2 * t]     += out0[t].x;
            h0[lane * 33 + 2 * t + 1] += out0[t].y;
            h1[lane * 33 + 2 * t]     += out1[t].x;
            h1[lane * 33 + 2 * t + 1] += out1[t].y;
        }
    }
}

extern __shared__ float smem[];

__global__ __launch_bounds__(256, 1)
void mixer_kernel(
    const float* __restrict__ x,
    const float* __restrict__ conv_w, const float* __restrict__ conv_b,
    const float* __restrict__ fc0_w,  const float* __restrict__ fc0_b,
    const float* __restrict__ ln1_g,  const float* __restrict__ ln1_b,
    const float* __restrict__ w11,    const float* __restrict__ b11,
    const float* __restrict__ w12,    const float* __restrict__ b12,
    const float* __restrict__ ln2_g,  const float* __restrict__ ln2_b,
    const float* __restrict__ w21,    const float* __restrict__ b21,
    const float* __restrict__ w22,    const float* __restrict__ b22,
    const float* __restrict__ fc1_w,  const float* __restrict__ fc1_b,
    const float* __restrict__ fcout_w,const float* __restrict__ fcout_b,
    float* __restrict__ out, int B)
{
    const int tid = threadIdx.x;
    const int lane = tid & 31;
    const int wid = tid >> 5;

    float* sW11  = smem + OFF_W11;
    float* sW12T = smem + OFF_W12T;
    float* sW21  = smem + OFF_W21;
    float* sW22T = smem + OFF_W22T;
    float* sB11  = smem + OFF_B11;
    float* sB12  = smem + OFF_B12;
    float* sB21  = smem + OFF_B21;
    float* sB22  = smem + OFF_B22;
    float* sLn1g = smem + OFF_LN1G;
    float* sLn1b = smem + OFF_LN1B;
    float* sLn2g = smem + OFF_LN2G;
    float* sLn2b = smem + OFF_LN2B;
    float* sH    = smem + OFF_H;
    float* sStats= smem + OFF_STATS;

    const int e0 = blockIdx.x * 16 + wid * 2;
    const int e1 = e0 + 1;
    const bool act0 = (e0 < B), act1 = (e1 < B);
    float* h0 = sH + (wid * 2) * 1056;
    float* h1 = h0 + 1056;
    float* st0 = sStats + wid * 128;
    float* st1 = st0 + 64;

    // ---- stage fc0 weights, then preprocess (conv1x1 + fc0) ----
    for (int i = tid; i < 1024; i += 256) sW11[i] = fc0_w[i];
    if (tid < 32) sB11[tid] = fc0_b[tid];
    __syncthreads();

    {
        const float cw0 = conv_w[0], cw1 = conv_w[1], cw2 = conv_w[2];
        const float cb  = conv_b[0];
        #pragma unroll
        for (int e = 0; e < 2; e++) {
            const int eb = e0 + e;
            if (eb >= B) break;
            float* hh = e ? h1 : h0;
            const float* xb = x + (size_t)eb * 3072 + lane * 32;
            float2 gp[16];
            #pragma unroll
            for (int q = 0; q < 8; q++) {
                float4 v0 = *reinterpret_cast<const float4*>(xb + q * 4);
                float4 v1 = *reinterpret_cast<const float4*>(xb + 1024 + q * 4);
                float4 v2 = *reinterpret_cast<const float4*>(xb + 2048 + q * 4);
                float g0 = cw0 * v0.x + cw1 * v1.x + cw2 * v2.x + cb;
                float g1 = cw0 * v0.y + cw1 * v1.y + cw2 * v2.y + cb;
                float g2 = cw0 * v0.z + cw1 * v1.z + cw2 * v2.z + cb;
                float g3 = cw0 * v0.w + cw1 * v1.w + cw2 * v2.w + cb;
                gp[2 * q]     = make_float2(g0, g1);
                gp[2 * q + 1] = make_float2(g2, g3);
            }
            for (int j = 0; j < 32; j++) {
                const float4* wq = reinterpret_cast<const float4*>(sW11 + j * 32);
                float2 acc = make_float2(0.f, 0.f), accb = make_float2(0.f, 0.f);
                #pragma unroll
                for (int q = 0; q < 8; q++) {
                    float4 w = wq[q];
                    acc  = ffma2(gp[2 * q],     make_float2(w.x, w.y), acc);
                    accb = ffma2(gp[2 * q + 1], make_float2(w.z, w.w), accb);
                }
                hh[lane * 33 + j] = acc.x + acc.y + accb.x + accb.y + sB11[j];
            }
        }
    }
    __syncthreads();

    // ---- 8 layers x 2 repeats ----
    for (int l = 0; l < 8; l++) {
        // stage this layer's weights (w12/w22 transposed to [256][36])
        {
            const float4* s1 = reinterpret_cast<const float4*>(w11 + l * 8192);
            float4* d1 = reinterpret_cast<float4*>(sW11);
            for (int i = tid; i < 2048; i += 256) d1[i] = s1[i];
            const float4* s2 = reinterpret_cast<const float4*>(w21 + l * 8192);
            float4* d2 = reinterpret_cast<float4*>(sW21);
            for (int i = tid; i < 2048; i += 256) d2[i] = s2[i];
            const float* g12 = w12 + l * 8192;
            for (int i = tid; i < 8192; i += 256) {
                int d = i & 255, k = i >> 8;
                sW12T[d * 36 + k] = g12[i];
            }
            const float* g22 = w22 + l * 8192;
            for (int i = tid; i < 8192; i += 256) {
                int d = i & 255, k = i >> 8;
                sW22T[d * 36 + k] = g22[i];
            }
            if (tid < 256) { sB11[tid] = b11[l * 256 + tid]; sB21[tid] = b21[l * 256 + tid]; }
            if (tid < 32) {
                sB12[tid]  = b12[l * 32 + tid];
                sB22[tid]  = b22[l * 32 + tid];
                sLn1g[tid] = ln1_g[l * 32 + tid];
                sLn1b[tid] = ln1_b[l * 32 + tid];
                sLn2g[tid] = ln2_g[l * 32 + tid];
                sLn2b[tid] = ln2_b[l * 32 + tid];
            }
        }
        __syncthreads();

        for (int rep = 0; rep < 2; rep++) {
            mix_branch<true >(h0, h1, sW11, sW12T, sB11, sB12, sLn1g, sLn1b, st0, st1, lane);
            __syncwarp();
            mix_branch<false>(h0, h1, sW21, sW22T, sB21, sB22, sLn2g, sLn2b, st0, st1, lane);
            __syncwarp();
        }
        __syncthreads();
    }

    // ---- head: fc1 + hardswish + avgpool(32) + fcout ----
    {
        const float4* s1 = reinterpret_cast<const float4*>(fc1_w);
        float4* d1 = reinterpret_cast<float4*>(sW11);
        for (int i = tid; i < 1024; i += 256) d1[i] = s1[i];
        for (int i = tid; i < 1280; i += 256) sW21[i] = fcout_w[i];
        if (tid < 128) sB11[tid] = fc1_b[tid];
        if (tid < 10)  sB12[tid] = fcout_b[tid];
    }
    __syncthreads();

    #pragma unroll
    for (int e = 0; e < 2; e++) {
        const bool act = e ? act1 : act0;
        if (!act) break;
        float* hh = e ? h1 : h0;
        float2 ap[16];
        #pragma unroll
        for (int t = 0; t < 16; t++)
            ap[t] = make_float2(hh[lane * 33 + 2 * t], hh[lane * 33 + 2 * t + 1]);
        float pool[4] = {0.f, 0.f, 0.f, 0.f};
        for (int d = 0; d < 128; d++) {
            const float4* wq = reinterpret_cast<const float4*>(sW11 + d * 32);
            float2 acc = make_float2(0.f, 0.f), accb = make_float2(0.f, 0.f);
            #pragma unroll
            for (int q = 0; q < 8; q++) {
                float4 w = wq[q];
                acc  = ffma2(ap[2 * q],     make_float2(w.x, w.y), acc);
                accb = ffma2(ap[2 * q + 1], make_float2(w.z, w.w), accb);
            }
            float y = hswish(acc.x + acc.y + accb.x + accb.y + sB11[d]);
            pool[d >> 5] += y;
        }
        #pragma unroll
        for (int p = 0; p < 4; p++) pool[p] *= (1.0f / 32.0f);
        const int eb = e ? e1 : e0;
        #pragma unroll
        for (int o = 0; o < 10; o++) {
            float4 wv = *reinterpret_cast<const float4*>(sW21 + o * 128 + lane * 4);
            float v = pool[0] * wv.x + pool[1] * wv.y + pool[2] * wv.z + pool[3] * wv.w;
            #pragma unroll
            for (int s = 16; s > 0; s >>= 1)
                v += __shfl_xor_sync(0xffffffffu, v, s);
            if (lane == 0) out[(size_t)eb * 10 + o] = v + sB12[o];
        }
    }
}

extern "C" void kernel_launch(void* const* d_in, const int* in_sizes, int n_in,
                              void* d_out, int out_size) {
    const float* x       = (const float*)d_in[0];
    const float* conv_w  = (const float*)d_in[1];
    const float* conv_b  = (const float*)d_in[2];
    const float* fc0_w   = (const float*)d_in[3];
    const float* fc0_b   = (const float*)d_in[4];
    const float* ln1_g   = (const float*)d_in[5];
    const float* ln1_b   = (const float*)d_in[6];
    const float* w11     = (const float*)d_in[7];
    const float* b11     = (const float*)d_in[8];
    const float* w12     = (const float*)d_in[9];
    const float* b12     = (const float*)d_in[10];
    const float* ln2_g   = (const float*)d_in[11];
    const float* ln2_b   = (const float*)d_in[12];
    const float* w21     = (const float*)d_in[13];
    const float* b21     = (const float*)d_in[14];
    const float* w22     = (const float*)d_in[15];
    const float* b22     = (const float*)d_in[16];
    const float* fc1_w   = (const float*)d_in[17];
    const float* fc1_b   = (const float*)d_in[18];
    const float* fcout_w = (const float*)d_in[19];
    const float* fcout_b = (const float*)d_in[20];
    float* out = (float*)d_out;

    const int B = in_sizes[0] / 3072;   // 3*32*32 floats per element
    const int blocks = (B + 15) / 16;
    const size_t smem_bytes = (size_t)SMEM_FLOATS * sizeof(float);

    cudaFuncSetAttribute(mixer_kernel,
                         cudaFuncAttributeMaxDynamicSharedMemorySize,
                         (int)smem_bytes);
    mixer_kernel<<<blocks, 256, smem_bytes>>>(
        x, conv_w, conv_b, fc0_w, fc0_b, ln1_g, ln1_b,
        w11, b11, w12, b12, ln2_g, ln2_b, w21, b21, w22, b22,
        fc1_w, fc1_b, fcout_w, fcout_b, out, B);
}